// round 1
// baseline (speedup 1.0000x reference)
#include <cuda_runtime.h>

// MoEGate: logits = X[T,H] @ W[E,H]^T ; softmax; top-8; renormalize.
// T=16384, H=2048, E=64, K=8.
// Output layout (float32): [T*8] topk weights, then [T*8] topk indices (as float).

#define H_DIM 2048
#define N_EXP 64
#define TOPK  8

#define BM 128
#define BN 64
#define BK 32
#define NTHREADS 256

__device__ __forceinline__ unsigned long long ffma2(unsigned long long a,
                                                    unsigned long long b,
                                                    unsigned long long c) {
    unsigned long long d;
    asm("fma.rn.f32x2 %0, %1, %2, %3;" : "=l"(d) : "l"(a), "l"(b), "l"(c));
    return d;
}

__device__ __forceinline__ unsigned long long pack2(float lo, float hi) {
    unsigned long long r;
    asm("mov.b64 %0, {%1, %2};" : "=l"(r) : "f"(lo), "f"(hi));
    return r;
}

__device__ __forceinline__ void unpack2(unsigned long long v, float& lo, float& hi) {
    asm("mov.b64 {%0, %1}, %2;" : "=f"(lo), "=f"(hi) : "l"(v));
}

__global__ __launch_bounds__(NTHREADS, 1)
void moe_gate_kernel(const float* __restrict__ X,   // [T, H]
                     const float* __restrict__ W,   // [E, H]
                     float* __restrict__ out,       // [T*8 weights][T*8 idx]
                     int T) {
    // Padded shared tiles (transposed: [k][m] / [k][n]) for conflict-free frag loads.
    __shared__ float Xs[BK][BM + 2];   // stride 130 (even -> 8B-aligned float2 loads)
    __shared__ float Ws[BK][BN + 2];   // stride 66
    __shared__ float logits[BM][BN + 1];

    const int tid = threadIdx.x;
    const int tx = tid & 15;    // expert dir: experts tx*4 .. tx*4+3
    const int ty = tid >> 4;    // token dir : tokens  ty*8 .. ty*8+7
    const int block_m = blockIdx.x * BM;

    // Global load mapping
    const int xrow  = tid >> 1;          // 0..127 (token within block)
    const int xcol0 = (tid & 1) * 16;    // 0 or 16
    const int wrow  = tid >> 2;          // 0..63 (expert)
    const int wcol0 = (tid & 3) * 8;     // 0,8,16,24

    const float* Xg = X + (long long)(block_m + xrow) * H_DIM + xcol0;
    const float* Wg = W + (long long)wrow * H_DIM + wcol0;

    // accumulators: acc[expert j][token-pair i] = f32x2 (tokens ty*8+2i, ty*8+2i+1)
    unsigned long long acc[4][4];
#pragma unroll
    for (int j = 0; j < 4; j++)
#pragma unroll
        for (int i = 0; i < 4; i++) acc[j][i] = 0ull;

    float4 xreg[4];
    float4 wreg[2];

    // prefetch first tile
#pragma unroll
    for (int q = 0; q < 4; q++) xreg[q] = *reinterpret_cast<const float4*>(Xg + 4 * q);
#pragma unroll
    for (int q = 0; q < 2; q++) wreg[q] = *reinterpret_cast<const float4*>(Wg + 4 * q);

    for (int kt = 0; kt < H_DIM; kt += BK) {
        // store prefetched regs to smem (transposed)
#pragma unroll
        for (int q = 0; q < 4; q++) {
            Xs[xcol0 + 4 * q + 0][xrow] = xreg[q].x;
            Xs[xcol0 + 4 * q + 1][xrow] = xreg[q].y;
            Xs[xcol0 + 4 * q + 2][xrow] = xreg[q].z;
            Xs[xcol0 + 4 * q + 3][xrow] = xreg[q].w;
        }
#pragma unroll
        for (int q = 0; q < 2; q++) {
            Ws[wcol0 + 4 * q + 0][wrow] = wreg[q].x;
            Ws[wcol0 + 4 * q + 1][wrow] = wreg[q].y;
            Ws[wcol0 + 4 * q + 2][wrow] = wreg[q].z;
            Ws[wcol0 + 4 * q + 3][wrow] = wreg[q].w;
        }
        __syncthreads();

        // prefetch next tile (LDGs issued before compute; latency hidden by FMA work)
        if (kt + BK < H_DIM) {
#pragma unroll
            for (int q = 0; q < 4; q++)
                xreg[q] = *reinterpret_cast<const float4*>(Xg + kt + BK + 4 * q);
#pragma unroll
            for (int q = 0; q < 2; q++)
                wreg[q] = *reinterpret_cast<const float4*>(Wg + kt + BK + 4 * q);
        }

        // compute BK k-steps
#pragma unroll 4
        for (int k = 0; k < BK; k++) {
            unsigned long long xp[4];
#pragma unroll
            for (int i = 0; i < 4; i++)
                xp[i] = *reinterpret_cast<const unsigned long long*>(&Xs[k][ty * 8 + 2 * i]);
#pragma unroll
            for (int j = 0; j < 4; j++) {
                float w = Ws[k][tx * 4 + j];
                unsigned long long wd = pack2(w, w);
#pragma unroll
                for (int i = 0; i < 4; i++) acc[j][i] = ffma2(xp[i], wd, acc[j][i]);
            }
        }
        __syncthreads();
    }

    // write logits tile to smem
#pragma unroll
    for (int j = 0; j < 4; j++) {
#pragma unroll
        for (int i = 0; i < 4; i++) {
            float lo, hi;
            unpack2(acc[j][i], lo, hi);
            logits[ty * 8 + 2 * i + 0][tx * 4 + j] = lo;
            logits[ty * 8 + 2 * i + 1][tx * 4 + j] = hi;
        }
    }
    __syncthreads();

    // fused epilogue: top-8 of logits (== top-8 of softmax), then softmax over
    // the selected 8 (full-softmax denominator cancels under renormalization).
    if (tid < BM) {
        float* row = logits[tid];
        float vals[TOPK];
        int   idxs[TOPK];
#pragma unroll
        for (int r = 0; r < TOPK; r++) {
            float best = -__int_as_float(0x7f800000);  // -inf
            int bi = 0;
            for (int e = 0; e < N_EXP; e++) {
                float v = row[e];
                if (v > best) { best = v; bi = e; }   // strict '>' => lowest index on ties
            }
            vals[r] = best;
            idxs[r] = bi;
            row[bi] = -__int_as_float(0x7f800000);
        }
        const float m0 = vals[0];
        float w[TOPK];
        float s = 0.f;
#pragma unroll
        for (int r = 0; r < TOPK; r++) { w[r] = __expf(vals[r] - m0); s += w[r]; }
        const float inv = 1.f / s;

        const long long gtok = block_m + tid;
#pragma unroll
        for (int r = 0; r < TOPK; r++) {
            out[gtok * TOPK + r] = w[r] * inv;
            out[(long long)T * TOPK + gtok * TOPK + r] = (float)idxs[r];
        }
    }
}

extern "C" void kernel_launch(void* const* d_in, const int* in_sizes, int n_in,
                              void* d_out, int out_size) {
    const float* X = (const float*)d_in[0];   // hidden_states [4,4096,2048] fp32
    const float* W = (const float*)d_in[1];   // weight [64,2048] fp32
    float* out = (float*)d_out;

    const int T = in_sizes[0] / H_DIM;        // 16384
    const int grid = T / BM;                  // 128

    moe_gate_kernel<<<grid, NTHREADS>>>(X, W, out, T);
}